// round 9
// baseline (speedup 1.0000x reference)
#include <cuda_runtime.h>
#include <cuda_bf16.h>
#include <stdint.h>
#include <math.h>

// ---------------- problem constants ----------------
#define NB    16
#define NCH   5
#define HIMG  256
#define WIMG  256
#define PP    8
#define SEQ   1024
#define NT    16384
#define PD    320
#define SF    64
#define ED    128
#define HS    512
#define NHD   4
#define HDIM  128
#define FF    2048
#define NE    6
#define NS    2
#define NLAY  4
#define NCLS  2

#define TS    40        // smem k-stride (bf16 elems): 80B rows, 16B aligned, ldmatrix conflict-free
#define ABYTES 10240    // 128*TS*2 bytes (one 128x32 bf16 tile)
#define BUFBYTES 40960  // A_hi + A_lo + W_hi + W_lo
#define SMEM_TOTAL (2*BUFBYTES)

// ---------------- fp32 scratch ----------------
__device__ float g_z[NT * ED];
__device__ float g_h[NT * HS];
__device__ float g_scores[(size_t)NB * NHD * SEQ * SEQ];
__device__ float g_a[NT * HS];
__device__ float g_spec[NT * HS];
__device__ float g_m[NT * HS];
__device__ float g_sp[NT * NS];
__device__ int   g_eidx[NE * NT];
__device__ float g_ewt[NE * NT];
__device__ int   g_ecnt[NE];
__device__ float g_pool[NB * HS];

// ---------------- bf16 split activations ----------------
__device__ __nv_bfloat16 b_t_hi[NT * PD],  b_t_lo[NT * PD];
__device__ __nv_bfloat16 b_z1_hi[NT * SF], b_z1_lo[NT * SF];
__device__ __nv_bfloat16 b_z_hi[NT * ED],  b_z_lo[NT * ED];
__device__ __nv_bfloat16 b_h_hi[NT * HS],  b_h_lo[NT * HS];
__device__ __nv_bfloat16 b_qkv_hi[NT * 3 * HS], b_qkv_lo[NT * 3 * HS];
__device__ __nv_bfloat16 b_sc_hi[(size_t)NB * NHD * SEQ * SEQ];
__device__ __nv_bfloat16 b_sc_lo[(size_t)NB * NHD * SEQ * SEQ];
__device__ __nv_bfloat16 b_at_hi[NT * HS], b_at_lo[NT * HS];
__device__ __nv_bfloat16 b_hid_hi[NT * FF], b_hid_lo[NT * FF];

// ---------------- bf16 split weights ----------------
__device__ __nv_bfloat16 w_tok1_hi[SF * PD], w_tok1_lo[SF * PD];
__device__ __nv_bfloat16 w_tok2_hi[ED * SF], w_tok2_lo[ED * SF];
__device__ __nv_bfloat16 w_proj_hi[HS * ED], w_proj_lo[HS * ED];
__device__ __nv_bfloat16 w_qkv_hi[NLAY * 3 * HS * HS], w_qkv_lo[NLAY * 3 * HS * HS];
__device__ __nv_bfloat16 w_wo_hi[NLAY * HS * HS], w_wo_lo[NLAY * HS * HS];
__device__ __nv_bfloat16 w_sf1_hi[NLAY * NE * FF * HS], w_sf1_lo[NLAY * NE * FF * HS];
__device__ __nv_bfloat16 w_sf2_hi[NLAY * NE * HS * FF], w_sf2_lo[NLAY * NE * HS * FF];
__device__ __nv_bfloat16 w_hf1_hi[NLAY * NS * FF * HS], w_hf1_lo[NLAY * NS * FF * HS];
__device__ __nv_bfloat16 w_hf2_hi[NLAY * NS * HS * FF], w_hf2_lo[NLAY * NS * HS * FF];

// ---------------- helpers ----------------
__device__ __forceinline__ float warp_sum(float v) {
    #pragma unroll
    for (int o = 16; o; o >>= 1) v += __shfl_xor_sync(0xffffffffu, v, o);
    return v;
}
__device__ __forceinline__ float warp_max(float v) {
    #pragma unroll
    for (int o = 16; o; o >>= 1) v = fmaxf(v, __shfl_xor_sync(0xffffffffu, v, o));
    return v;
}
__device__ __forceinline__ void ldsm4(unsigned int* r, unsigned int addr) {
    asm volatile("ldmatrix.sync.aligned.m8n8.x4.shared.b16 {%0,%1,%2,%3}, [%4];"
                 : "=r"(r[0]), "=r"(r[1]), "=r"(r[2]), "=r"(r[3]) : "r"(addr));
}
__device__ __forceinline__ void mma16816(float* c, const unsigned int* a, const unsigned int* b) {
    asm volatile("mma.sync.aligned.m16n8k16.row.col.f32.bf16.bf16.f32 "
                 "{%0,%1,%2,%3}, {%4,%5,%6,%7}, {%8,%9}, {%0,%1,%2,%3};"
                 : "+f"(c[0]), "+f"(c[1]), "+f"(c[2]), "+f"(c[3])
                 : "r"(a[0]), "r"(a[1]), "r"(a[2]), "r"(a[3]), "r"(b[0]), "r"(b[1]));
}
#define CP16(dst, src) asm volatile("cp.async.cg.shared.global [%0], [%1], 16;" :: "r"(dst), "l"(src))
#define CP_COMMIT() asm volatile("cp.async.commit_group;")

__device__ __forceinline__ void split2(float a, float b,
                                       __nv_bfloat16* hi, __nv_bfloat16* lo) {
    __nv_bfloat162 hp, lp;
    hp.x = __float2bfloat16(a); hp.y = __float2bfloat16(b);
    lp.x = __float2bfloat16(a - __bfloat162float(hp.x));
    lp.y = __float2bfloat16(b - __bfloat162float(hp.y));
    *(__nv_bfloat162*)hi = hp;
    *(__nv_bfloat162*)lo = lp;
}

// ---------------- weight/act split kernel (vectorized) ----------------
__global__ void split_kernel(const float4* __restrict__ src,
                             __nv_bfloat16* __restrict__ hi,
                             __nv_bfloat16* __restrict__ lo, int n4) {
    int i = blockIdx.x * blockDim.x + threadIdx.x;
    if (i >= n4) return;
    float4 v = src[i];
    split2(v.x, v.y, hi + i * 4,     lo + i * 4);
    split2(v.z, v.w, hi + i * 4 + 2, lo + i * 4 + 2);
}

// ---------------- patch extraction (writes split) ----------------
__global__ void patchify_kernel(const float* __restrict__ x) {
    int idx = blockIdx.x * blockDim.x + threadIdx.x;
    if (idx >= NT * PD) return;
    int n = idx / PD, f = idx % PD;
    int b = n / SEQ, s = n % SEQ;
    int sh = s >> 5, sw = s & 31;
    int c = f >> 6, r = f & 63;
    int pi = r >> 3, pj = r & 7;
    float v = x[(((size_t)(b * NCH + c) * HIMG + (sh * PP + pi)) * WIMG) + (sw * PP + pj)];
    __nv_bfloat16 h = __float2bfloat16(v);
    b_t_hi[idx] = h;
    b_t_lo[idx] = __float2bfloat16(v - __bfloat162float(h));
}

// ---------------- positional encoding add ----------------
__global__ void add_pe_kernel() {
    int idx = blockIdx.x * blockDim.x + threadIdx.x;
    if (idx >= NT * ED) return;
    int n = idx >> 7, d = idx & 127;
    int s = n & (SEQ - 1);
    int i2 = d & ~1;
    float div = expf(-(float)i2 * (9.2103403719761836f / (float)ED));
    float arg = (float)s * div;
    float pe = (d & 1) ? cosf(arg) : sinf(arg);
    float v = g_z[idx] + pe;
    __nv_bfloat16 h = __float2bfloat16(v);
    b_z_hi[idx] = h;
    b_z_lo[idx] = __float2bfloat16(v - __bfloat162float(h));
}

// ================= tensor-core GEMM (bf16 split, cp.async double-buffered) =================
// BM=128 BN=128 BK=32, 256 threads, 8 warps (2m x 4n), warp tile 64x32, 3-MMA split.
// MODE 0: generic TN. MODE 1: QK^T batched. MODE 2: AV batched (V transposed in stage).
// OUT 0: fp32 C. OUT 1: split bf16. OUT 2: both. SCATTER: fp32 += wgt*(acc+bias).
template<int MODE, int ACT, int SCATTER, int OUT>
__global__ __launch_bounds__(256) void tgemm(
    const __nv_bfloat16* __restrict__ Ahi, const __nv_bfloat16* __restrict__ Alo,
    const __nv_bfloat16* __restrict__ Whi, const __nv_bfloat16* __restrict__ Wlo,
    const float* __restrict__ bias, float* __restrict__ C,
    __nv_bfloat16* __restrict__ Chi, __nv_bfloat16* __restrict__ Clo,
    int M, int N, int K,
    const int* __restrict__ gidx, const int* __restrict__ mcnt,
    const int* __restrict__ sidx, const float* __restrict__ wv, int ws)
{
    const __nv_bfloat16 *Abh, *Abl, *Wbh, *Wbl;
    int lda, ldw, ldc;
    size_t cbase = 0;
    if (MODE == 1) {
        int z = blockIdx.z; int b = z >> 2, h = z & 3;
        size_t qo = (size_t)b * SEQ * (3 * HS) + h * HDIM;
        Abh = Ahi + qo;            Abl = Alo + qo;            lda = 3 * HS;
        Wbh = Ahi + qo + HS;       Wbl = Alo + qo + HS;       ldw = 3 * HS;
        cbase = (size_t)z * SEQ * SEQ;                         ldc = SEQ;
    } else if (MODE == 2) {
        int z = blockIdx.z; int b = z >> 2, h = z & 3;
        size_t so = (size_t)z * SEQ * SEQ;
        size_t vo = (size_t)b * SEQ * (3 * HS) + 2 * HS + h * HDIM;
        Abh = Ahi + so; Abl = Alo + so;  lda = SEQ;
        Wbh = Whi + vo; Wbl = Wlo + vo;  ldw = 3 * HS;
        cbase = (size_t)b * SEQ * HS + h * HDIM;  ldc = HS;
    } else {
        Abh = Ahi; Abl = Alo; Wbh = Whi; Wbl = Wlo;
        lda = K; ldw = K; ldc = N;
    }

    int Mr = (MODE == 0 && mcnt) ? *mcnt : M;
    int m0 = blockIdx.y * 128;
    int n0 = blockIdx.x * 128;
    if (m0 >= Mr) return;

    extern __shared__ __align__(16) char smem[];
    __shared__ int ridx[128];
    __shared__ int widx[128];

    int tid = threadIdx.x;
    int warp = tid >> 5, L = tid & 31;
    int warp_m = warp >> 2, warp_n = warp & 3;

    if (tid < 128) {
        int r = m0 + tid;
        if (r > Mr - 1) r = Mr - 1;
        ridx[tid] = (MODE == 0 && gidx) ? gidx[r] : r;
        int wr = n0 + tid;
        if (wr > N - 1) wr = N - 1;
        widx[tid] = wr;
    }
    __syncthreads();

    unsigned int sbase = (unsigned int)__cvta_generic_to_shared(smem);

    // ldmatrix per-lane offsets (element units)
    int rowA = ((L >> 3) & 1) * 8 + (L & 7);
    int kA   = ((L >> 4) & 1) * 8;
    int rowB = ((L >> 4) & 1) * 8 + (L & 7);
    int kB   = ((L >> 3) & 1) * 8;
    int offA[4], offB[2];
    #pragma unroll
    for (int mi = 0; mi < 4; mi++) offA[mi] = (warp_m * 64 + mi * 16 + rowA) * TS + kA;
    #pragma unroll
    for (int nb = 0; nb < 2; nb++) offB[nb] = (warp_n * 32 + nb * 16 + rowB) * TS + kB;

    auto stage = [&](int buf, int kk) {
        unsigned int aH = sbase + buf * BUFBYTES;
        unsigned int aL = aH + ABYTES;
        unsigned int wH = aH + 2 * ABYTES;
        unsigned int wL = aH + 3 * ABYTES;
        #pragma unroll
        for (int i = 0; i < 2; i++) {
            int f = tid + i * 256;
            int r = f >> 2, c8 = (f & 3) * 8;
            size_t so = (size_t)ridx[r] * lda + kk + c8;
            unsigned int d = (unsigned int)((r * TS + c8) * 2);
            CP16(aH + d, Abh + so);
            CP16(aL + d, Abl + so);
        }
        if (MODE == 2) {
            // V transposed staging: bf16x2 scalar stores, 128 n-cols x 32 k
            __nv_bfloat16* swh = (__nv_bfloat16*)(smem + buf * BUFBYTES + 2 * ABYTES);
            __nv_bfloat16* swl = (__nv_bfloat16*)(smem + buf * BUFBYTES + 3 * ABYTES);
            #pragma unroll
            for (int j = 0; j < 8; j++) {
                int idx = tid + j * 256;      // 2048 bf16x2 pairs
                int k = idx >> 6, n2 = (idx & 63) * 2;
                size_t so = (size_t)(kk + k) * ldw + n0 + n2;
                __nv_bfloat162 vh = *(const __nv_bfloat162*)(Wbh + so);
                __nv_bfloat162 vl = *(const __nv_bfloat162*)(Wbl + so);
                swh[n2 * TS + k] = vh.x; swh[(n2 + 1) * TS + k] = vh.y;
                swl[n2 * TS + k] = vl.x; swl[(n2 + 1) * TS + k] = vl.y;
            }
        } else {
            #pragma unroll
            for (int i = 0; i < 2; i++) {
                int f = tid + i * 256;
                int r = f >> 2, c8 = (f & 3) * 8;
                size_t so = (size_t)widx[r] * ldw + kk + c8;
                unsigned int d = (unsigned int)((r * TS + c8) * 2);
                CP16(wH + d, Wbh + so);
                CP16(wL + d, Wbl + so);
            }
        }
    };

    float acc[4][4][4] = {};
    int KT = K / 32;

    stage(0, 0);
    CP_COMMIT();

    for (int kt = 0; kt < KT; kt++) {
        int cur = kt & 1;
        if (kt + 1 < KT) {
            stage(cur ^ 1, (kt + 1) * 32);
            CP_COMMIT();
            asm volatile("cp.async.wait_group 1;");
        } else {
            asm volatile("cp.async.wait_group 0;");
        }
        __syncthreads();

        unsigned int aH = sbase + cur * BUFBYTES;
        unsigned int aL = aH + ABYTES;
        unsigned int wH = aH + 2 * ABYTES;
        unsigned int wL = aH + 3 * ABYTES;

        #pragma unroll
        for (int ks = 0; ks < 32; ks += 16) {
            unsigned int ah[4][4], al[4][4], bh[2][4], bl[2][4];
            #pragma unroll
            for (int mi = 0; mi < 4; mi++) {
                ldsm4(ah[mi], aH + (unsigned int)(offA[mi] + ks) * 2u);
                ldsm4(al[mi], aL + (unsigned int)(offA[mi] + ks) * 2u);
            }
            #pragma unroll
            for (int nb = 0; nb < 2; nb++) {
                ldsm4(bh[nb], wH + (unsigned int)(offB[nb] + ks) * 2u);
                ldsm4(bl[nb], wL + (unsigned int)(offB[nb] + ks) * 2u);
            }
            #pragma unroll
            for (int mi = 0; mi < 4; mi++)
                #pragma unroll
                for (int ni = 0; ni < 4; ni++) {
                    int nb = ni >> 1, sel = (ni & 1) * 2;
                    mma16816(acc[mi][ni], ah[mi], &bh[nb][sel]);
                    mma16816(acc[mi][ni], ah[mi], &bl[nb][sel]);
                    mma16816(acc[mi][ni], al[mi], &bh[nb][sel]);
                }
        }
        __syncthreads();
    }

    // ---- epilogue ----
    #pragma unroll
    for (int mi = 0; mi < 4; mi++) {
        #pragma unroll
        for (int hh = 0; hh < 2; hh++) {
            int m = m0 + warp_m * 64 + mi * 16 + (L >> 2) + hh * 8;
            if (m >= Mr) continue;
            int srow = 0; float wgt = 0.f;
            if (SCATTER) {
                srow = sidx ? sidx[m] : m;
                wgt = wv[(size_t)m * ws];
            }
            #pragma unroll
            for (int ni = 0; ni < 4; ni++) {
                int n = n0 + warp_n * 32 + ni * 8 + (L & 3) * 2;
                if (n >= N) continue;
                float v0 = acc[mi][ni][hh * 2 + 0];
                float v1 = acc[mi][ni][hh * 2 + 1];
                if (MODE == 0 && bias) { v0 += bias[n]; v1 += bias[n + 1]; }
                if (ACT == 1) { v0 = fmaxf(v0, 0.f); v1 = fmaxf(v1, 0.f); }
                if (ACT == 2) {
                    v0 = 0.5f * v0 * (1.f + erff(v0 * 0.70710678118654752f));
                    v1 = 0.5f * v1 * (1.f + erff(v1 * 0.70710678118654752f));
                }
                size_t ci = cbase + (size_t)(SCATTER ? srow : m) * ldc + n;
                if (SCATTER) {
                    C[ci] += wgt * v0;
                    C[ci + 1] += wgt * v1;
                } else {
                    if (OUT == 0 || OUT == 2) { C[ci] = v0; C[ci + 1] = v1; }
                    if (OUT == 1 || OUT == 2) split2(v0, v1, Chi + ci, Clo + ci);
                }
            }
        }
    }
}

// ---------------- attention softmax (fp32 in, split bf16 out) ----------------
__global__ __launch_bounds__(256) void attn_softmax_kernel() {
    size_t base = ((size_t)blockIdx.y * SEQ + blockIdx.x) * SEQ;
    const float* row = g_scores + base;
    const float scale = 0.08838834764831845f;
    int tid = threadIdx.x;
    __shared__ float sm[8];

    float2 p0 = *(const float2*)&row[2 * tid];
    float2 p1 = *(const float2*)&row[2 * tid + 512];
    float v[4] = {p0.x * scale, p0.y * scale, p1.x * scale, p1.y * scale};
    float mx = fmaxf(fmaxf(v[0], v[1]), fmaxf(v[2], v[3]));
    mx = warp_max(mx);
    if ((tid & 31) == 0) sm[tid >> 5] = mx;
    __syncthreads();
    float bm = sm[0];
    #pragma unroll
    for (int i = 1; i < 8; i++) bm = fmaxf(bm, sm[i]);
    __syncthreads();

    float s = 0.f;
    #pragma unroll
    for (int i = 0; i < 4; i++) { v[i] = expf(v[i] - bm); s += v[i]; }
    s = warp_sum(s);
    if ((tid & 31) == 0) sm[tid >> 5] = s;
    __syncthreads();
    float tot = 0.f;
    #pragma unroll
    for (int i = 0; i < 8; i++) tot += sm[i];
    float inv = 1.f / tot;
    split2(v[0] * inv, v[1] * inv, &b_sc_hi[base + 2 * tid], &b_sc_lo[base + 2 * tid]);
    split2(v[2] * inv, v[3] * inv, &b_sc_hi[base + 2 * tid + 512], &b_sc_lo[base + 2 * tid + 512]);
}

// ---------------- fused residual-add + layernorm (optional split out) ----------------
__global__ __launch_bounds__(128) void ln_add_kernel(
    const float* __restrict__ X, const float* __restrict__ Y,
    const float* __restrict__ gam, const float* __restrict__ bet,
    float* __restrict__ O, __nv_bfloat16* __restrict__ Ohi, __nv_bfloat16* __restrict__ Olo)
{
    size_t base = (size_t)blockIdx.x * HS;
    int tid = threadIdx.x;
    __shared__ float sm[4];
    float v[4];
    #pragma unroll
    for (int i = 0; i < 4; i++) { int d = tid + i * 128; v[i] = X[base + d] + Y[base + d]; }
    float s = v[0] + v[1] + v[2] + v[3];
    s = warp_sum(s);
    if ((tid & 31) == 0) sm[tid >> 5] = s;
    __syncthreads();
    float mean = (sm[0] + sm[1] + sm[2] + sm[3]) * (1.f / HS);
    __syncthreads();
    float q = 0.f;
    #pragma unroll
    for (int i = 0; i < 4; i++) { float d = v[i] - mean; q += d * d; }
    q = warp_sum(q);
    if ((tid & 31) == 0) sm[tid >> 5] = q;
    __syncthreads();
    float var = (sm[0] + sm[1] + sm[2] + sm[3]) * (1.f / HS);
    float inv = rsqrtf(var + 1e-5f);
    #pragma unroll
    for (int i = 0; i < 4; i++) {
        int d = tid + i * 128;
        float o = (v[i] - mean) * inv * gam[d] + bet[d];
        O[base + d] = o;
        if (Ohi) {
            __nv_bfloat16 h = __float2bfloat16(o);
            Ohi[base + d] = h;
            Olo[base + d] = __float2bfloat16(o - __bfloat162float(h));
        }
    }
}

// ---------------- routers ----------------
__global__ __launch_bounds__(256) void route_spec_kernel(const float* __restrict__ rw) {
    int warp = threadIdx.x >> 5, lane = threadIdx.x & 31;
    int token = blockIdx.x * 8 + warp;
    const float* hrow = g_h + (size_t)token * HS;
    float hv[16];
    #pragma unroll
    for (int j = 0; j < 16; j++) hv[j] = hrow[lane + j * 32];
    float logit[NE];
    #pragma unroll
    for (int e = 0; e < NE; e++) {
        const float* w = rw + e * HS;
        float p = 0.f;
        #pragma unroll
        for (int j = 0; j < 16; j++) p = fmaf(hv[j], w[lane + j * 32], p);
        logit[e] = warp_sum(p);
    }
    if (lane == 0) {
        float mx = logit[0];
        #pragma unroll
        for (int e = 1; e < NE; e++) mx = fmaxf(mx, logit[e]);
        float pr[NE], s = 0.f;
        #pragma unroll
        for (int e = 0; e < NE; e++) { pr[e] = expf(logit[e] - mx); s += pr[e]; }
        #pragma unroll
        for (int e = 0; e < NE; e++) pr[e] /= s;
        int i1 = 0;
        #pragma unroll
        for (int e = 1; e < NE; e++) if (pr[e] > pr[i1]) i1 = e;
        int i2 = (i1 == 0) ? 1 : 0;
        #pragma unroll
        for (int e = 0; e < NE; e++) if (e != i1 && pr[e] > pr[i2]) i2 = e;
        float den = pr[i1] + pr[i2] + 1e-9f;
        float w1 = pr[i1] / den, w2 = pr[i2] / den;
        int p1 = atomicAdd(&g_ecnt[i1], 1);
        g_eidx[i1 * NT + p1] = token; g_ewt[i1 * NT + p1] = w1;
        int p2 = atomicAdd(&g_ecnt[i2], 1);
        g_eidx[i2 * NT + p2] = token; g_ewt[i2 * NT + p2] = w2;
    }
}

__global__ __launch_bounds__(256) void route_shared_kernel(const float* __restrict__ rw) {
    int warp = threadIdx.x >> 5, lane = threadIdx.x & 31;
    int token = blockIdx.x * 8 + warp;
    const float* hrow = g_h + (size_t)token * HS;
    float hv[16];
    #pragma unroll
    for (int j = 0; j < 16; j++) hv[j] = hrow[lane + j * 32];
    float logit[NS];
    #pragma unroll
    for (int e = 0; e < NS; e++) {
        const float* w = rw + e * HS;
        float p = 0.f;
        #pragma unroll
        for (int j = 0; j < 16; j++) p = fmaf(hv[j], w[lane + j * 32], p);
        logit[e] = warp_sum(p);
    }
    if (lane == 0) {
        float mx = fmaxf(logit[0], logit[1]);
        float e0 = expf(logit[0] - mx), e1 = expf(logit[1] - mx);
        float inv = 1.f / (e0 + e1);
        g_sp[token * NS + 0] = e0 * inv;
        g_sp[token * NS + 1] = e1 * inv;
    }
}

// ---------------- pooling + head ----------------
__global__ void pool_mean_kernel() {
    int b = blockIdx.x, d = threadIdx.x;
    float s = 0.f;
    for (int t = 0; t < SEQ; t++) s += g_h[((size_t)b * SEQ + t) * HS + d];
    g_pool[b * HS + d] = s * (1.f / SEQ);
}

__global__ __launch_bounds__(128) void cls_head_kernel(
    const float* __restrict__ w, const float* __restrict__ bias, float* __restrict__ out)
{
    int n = blockIdx.x, b = blockIdx.y;
    int tid = threadIdx.x;
    __shared__ float sm[4];
    float p = 0.f;
    for (int j = tid; j < HS; j += 128) p = fmaf(g_pool[b * HS + j], w[n * HS + j], p);
    p = warp_sum(p);
    if ((tid & 31) == 0) sm[tid >> 5] = p;
    __syncthreads();
    if (tid == 0) out[b * NCLS + n] = sm[0] + sm[1] + sm[2] + sm[3] + bias[n];
}

// ---------------- host helpers ----------------
typedef __nv_bfloat16 bf16;

static void split_arr(const float* src, bf16* hi, bf16* lo, size_t n) {
    int n4 = (int)(n / 4);
    split_kernel<<<(n4 + 255) / 256, 256>>>((const float4*)src, hi, lo, n4);
}

template<int MODE, int ACT, int SCATTER, int OUT>
static void launch_tg(dim3 grid,
                      const bf16* Ahi, const bf16* Alo, const bf16* Whi, const bf16* Wlo,
                      const float* bias, float* C, bf16* Chi, bf16* Clo,
                      int M, int N, int K,
                      const int* gidx = nullptr, const int* mcnt = nullptr,
                      const int* sidx = nullptr, const float* wv = nullptr, int ws = 0)
{
    cudaFuncSetAttribute(tgemm<MODE, ACT, SCATTER, OUT>,
                         cudaFuncAttributeMaxDynamicSharedMemorySize, SMEM_TOTAL);
    tgemm<MODE, ACT, SCATTER, OUT><<<grid, 256, SMEM_TOTAL>>>(
        Ahi, Alo, Whi, Wlo, bias, C, Chi, Clo, M, N, K, gidx, mcnt, sidx, wv, ws);
}

#define SYM(T, p, s) T* p; cudaGetSymbolAddress((void**)&p, s)
#define NBLK(n) (((n) + 127) / 128)

extern "C" void kernel_launch(void* const* d_in, const int* in_sizes, int n_in,
                              void* d_out, int out_size)
{
    const float* x         = (const float*)d_in[0];
    const float* tok_w1    = (const float*)d_in[1];
    const float* tok_b1    = (const float*)d_in[2];
    const float* tok_w2    = (const float*)d_in[3];
    const float* tok_b2    = (const float*)d_in[4];
    const float* proj_w    = (const float*)d_in[5];
    const float* proj_b    = (const float*)d_in[6];
    const float* attn_wqkv = (const float*)d_in[7];
    const float* attn_bqkv = (const float*)d_in[8];
    const float* attn_wo   = (const float*)d_in[9];
    const float* attn_bo   = (const float*)d_in[10];
    const float* ln1_g     = (const float*)d_in[11];
    const float* ln1_b     = (const float*)d_in[12];
    const float* spec_rw   = (const float*)d_in[13];
    const float* spec_f1w  = (const float*)d_in[14];
    const float* spec_f1b  = (const float*)d_in[15];
    const float* spec_f2w  = (const float*)d_in[16];
    const float* spec_f2b  = (const float*)d_in[17];
    const float* shr_rw    = (const float*)d_in[18];
    const float* shr_f1w   = (const float*)d_in[19];
    const float* shr_f1b   = (const float*)d_in[20];
    const float* shr_f2w   = (const float*)d_in[21];
    const float* shr_f2b   = (const float*)d_in[22];
    const float* lnm_g     = (const float*)d_in[23];
    const float* lnm_b     = (const float*)d_in[24];
    const float* ln2_g     = (const float*)d_in[25];
    const float* ln2_b     = (const float*)d_in[26];
    const float* cls_w     = (const float*)d_in[27];
    const float* cls_b     = (const float*)d_in[28];
    float* out = (float*)d_out;

    SYM(float, pz, g_z);       SYM(float, ph, g_h);      SYM(float, pscores, g_scores);
    SYM(float, pa, g_a);       SYM(float, pspec, g_spec); SYM(float, pm, g_m);
    SYM(float, psp, g_sp);     SYM(float, pewt, g_ewt);
    SYM(int, peidx, g_eidx);   SYM(int, pecnt, g_ecnt);

    SYM(bf16, t_hi, b_t_hi);   SYM(bf16, t_lo, b_t_lo);
    SYM(bf16, z1_hi, b_z1_hi); SYM(bf16, z1_lo, b_z1_lo);
    SYM(bf16, z_hi, b_z_hi);   SYM(bf16, z_lo, b_z_lo);
    SYM(bf16, h_hi, b_h_hi);   SYM(bf16, h_lo, b_h_lo);
    SYM(bf16, qkv_hi, b_qkv_hi); SYM(bf16, qkv_lo, b_qkv_lo);
    SYM(bf16, sc_hi, b_sc_hi); SYM(bf16, sc_lo, b_sc_lo);
    SYM(bf16, at_hi, b_at_hi); SYM(bf16, at_lo, b_at_lo);
    SYM(bf16, hid_hi, b_hid_hi); SYM(bf16, hid_lo, b_hid_lo);

    SYM(bf16, tw1_hi, w_tok1_hi); SYM(bf16, tw1_lo, w_tok1_lo);
    SYM(bf16, tw2_hi, w_tok2_hi); SYM(bf16, tw2_lo, w_tok2_lo);
    SYM(bf16, pw_hi, w_proj_hi);  SYM(bf16, pw_lo, w_proj_lo);
    SYM(bf16, qw_hi, w_qkv_hi);   SYM(bf16, qw_lo, w_qkv_lo);
    SYM(bf16, ow_hi, w_wo_hi);    SYM(bf16, ow_lo, w_wo_lo);
    SYM(bf16, s1_hi, w_sf1_hi);   SYM(bf16, s1_lo, w_sf1_lo);
    SYM(bf16, s2_hi, w_sf2_hi);   SYM(bf16, s2_lo, w_sf2_lo);
    SYM(bf16, h1_hi, w_hf1_hi);   SYM(bf16, h1_lo, w_hf1_lo);
    SYM(bf16, h2_hi, w_hf2_hi);   SYM(bf16, h2_lo, w_hf2_lo);

    // ---- split all weights once per launch ----
    split_arr(tok_w1, tw1_hi, tw1_lo, (size_t)SF * PD);
    split_arr(tok_w2, tw2_hi, tw2_lo, (size_t)ED * SF);
    split_arr(proj_w, pw_hi, pw_lo, (size_t)HS * ED);
    split_arr(attn_wqkv, qw_hi, qw_lo, (size_t)NLAY * 3 * HS * HS);
    split_arr(attn_wo, ow_hi, ow_lo, (size_t)NLAY * HS * HS);
    split_arr(spec_f1w, s1_hi, s1_lo, (size_t)NLAY * NE * FF * HS);
    split_arr(spec_f2w, s2_hi, s2_lo, (size_t)NLAY * NE * HS * FF);
    split_arr(shr_f1w, h1_hi, h1_lo, (size_t)NLAY * NS * FF * HS);
    split_arr(shr_f2w, h2_hi, h2_lo, (size_t)NLAY * NS * HS * FF);

    // ---- tokenizer + projection ----
    patchify_kernel<<<(NT * PD + 255) / 256, 256>>>(x);
    launch_tg<0, 1, 0, 1>(dim3(NBLK(SF), NT / 128), t_hi, t_lo, tw1_hi, tw1_lo,
                          tok_b1, nullptr, z1_hi, z1_lo, NT, SF, PD);
    launch_tg<0, 1, 0, 0>(dim3(NBLK(ED), NT / 128), z1_hi, z1_lo, tw2_hi, tw2_lo,
                          tok_b2, pz, nullptr, nullptr, NT, ED, SF);
    add_pe_kernel<<<(NT * ED + 255) / 256, 256>>>();
    launch_tg<0, 0, 0, 2>(dim3(NBLK(HS), NT / 128), z_hi, z_lo, pw_hi, pw_lo,
                          proj_b, ph, h_hi, h_lo, NT, HS, ED);

    // ---- transformer layers ----
    for (int l = 0; l < NLAY; l++) {
        launch_tg<0, 0, 0, 1>(dim3(NBLK(3 * HS), NT / 128),
                              h_hi, h_lo, qw_hi + (size_t)l * 3 * HS * HS, qw_lo + (size_t)l * 3 * HS * HS,
                              attn_bqkv + (size_t)l * 3 * HS, nullptr, qkv_hi, qkv_lo,
                              NT, 3 * HS, HS);
        launch_tg<1, 0, 0, 0>(dim3(NBLK(SEQ), SEQ / 128, NB * NHD),
                              qkv_hi, qkv_lo, nullptr, nullptr,
                              nullptr, pscores, nullptr, nullptr, SEQ, SEQ, HDIM);
        attn_softmax_kernel<<<dim3(SEQ, NB * NHD), 256>>>();
        launch_tg<2, 0, 0, 1>(dim3(NBLK(HDIM), SEQ / 128, NB * NHD),
                              sc_hi, sc_lo, qkv_hi, qkv_lo,
                              nullptr, nullptr, at_hi, at_lo, SEQ, HDIM, SEQ);
        launch_tg<0, 0, 0, 0>(dim3(NBLK(HS), NT / 128),
                              at_hi, at_lo, ow_hi + (size_t)l * HS * HS, ow_lo + (size_t)l * HS * HS,
                              attn_bo + (size_t)l * HS, pa, nullptr, nullptr, NT, HS, HS);
        ln_add_kernel<<<NT, 128>>>(ph, pa, ln1_g + l * HS, ln1_b + l * HS, ph, h_hi, h_lo);

        // MoE
        cudaMemsetAsync(pecnt, 0, NE * sizeof(int));
        cudaMemsetAsync(pspec, 0, (size_t)NT * HS * sizeof(float));
        route_spec_kernel<<<NT / 8, 256>>>(spec_rw + (size_t)l * NE * HS);
        for (int e = 0; e < NE; e++) {
            size_t wo1 = (size_t)(l * NE + e) * FF * HS;
            size_t wo2 = (size_t)(l * NE + e) * HS * FF;
            launch_tg<0, 2, 0, 1>(dim3(NBLK(FF), NT / 128),
                                  h_hi, h_lo, s1_hi + wo1, s1_lo + wo1,
                                  spec_f1b + (size_t)(l * NE + e) * FF,
                                  nullptr, hid_hi, hid_lo, NT, FF, HS,
                                  peidx + e * NT, pecnt + e);
            launch_tg<0, 0, 1, 0>(dim3(NBLK(HS), NT / 128),
                                  hid_hi, hid_lo, s2_hi + wo2, s2_lo + wo2,
                                  spec_f2b + (size_t)(l * NE + e) * HS,
                                  pspec, nullptr, nullptr, NT, HS, FF,
                                  nullptr, pecnt + e, peidx + e * NT, pewt + e * NT, 1);
        }
        route_shared_kernel<<<NT / 8, 256>>>(shr_rw + (size_t)l * NS * HS);
        for (int e = 0; e < NS; e++) {
            size_t wo1 = (size_t)(l * NS + e) * FF * HS;
            size_t wo2 = (size_t)(l * NS + e) * HS * FF;
            launch_tg<0, 2, 0, 1>(dim3(NBLK(FF), NT / 128),
                                  h_hi, h_lo, h1_hi + wo1, h1_lo + wo1,
                                  shr_f1b + (size_t)(l * NS + e) * FF,
                                  nullptr, hid_hi, hid_lo, NT, FF, HS);
            launch_tg<0, 0, 1, 0>(dim3(NBLK(HS), NT / 128),
                                  hid_hi, hid_lo, h2_hi + wo2, h2_lo + wo2,
                                  shr_f2b + (size_t)(l * NS + e) * HS,
                                  pspec, nullptr, nullptr, NT, HS, FF,
                                  nullptr, nullptr, nullptr, psp + e, NS);
        }
        ln_add_kernel<<<NT, 128>>>(ph, pspec, lnm_g + l * HS, lnm_b + l * HS, pm, nullptr, nullptr);
        ln_add_kernel<<<NT, 128>>>(ph, pm, ln2_g + l * HS, ln2_b + l * HS, ph, h_hi, h_lo);
    }

    // ---- head ----
    pool_mean_kernel<<<NB, HS>>>();
    cls_head_kernel<<<dim3(NCLS, NB), 128>>>(cls_w, cls_b, out);
}